// round 2
// baseline (speedup 1.0000x reference)
#include <cuda_runtime.h>

#define D   16
#define LIB 969
#define TPB 256
#define ROWS_PER_BLOCK (2 * TPB)

__constant__ float c_coeff[LIB * D];        // masked coefficients, 62016 B
__device__   float g_masked[LIB * D];       // scratch: mask applied here first

// packed fp32x2 FMA: acc = m * c + acc (lanewise on two fp32 halves)
#define FFMA2(acc, m, c) \
    asm("fma.rn.f32x2 %0, %1, %2, %0;" : "+l"(acc) : "l"(m), "l"(c))
// packed fp32x2 MUL
#define MULX2(dst, a, b) \
    asm("mul.rn.f32x2 %0, %1, %2;" : "=l"(dst) : "l"(a), "l"(b))

// 128-bit load from constant space (dedicated constant port, not L1tex)
__device__ __forceinline__ ulonglong2 ldc_v2(unsigned long long caddr) {
    ulonglong2 r;
    asm("ld.const.v2.u64 {%0, %1}, [%2];" : "=l"(r.x), "=l"(r.y) : "l"(caddr));
    return r;
}

__global__ void prep_kernel(const float* __restrict__ coeff,
                            const float* __restrict__ fixedv,
                            const unsigned char* __restrict__ fmask)
{
    int i = blockIdx.x * blockDim.x + threadIdx.x;
    if (i < LIB * D) g_masked[i] = fmask[i] ? fixedv[i] : coeff[i];
}

__global__ __launch_bounds__(TPB, 3) void sindy_kernel(
    const float* __restrict__ z,
    float* __restrict__ out,
    int B)
{
    __shared__ unsigned long long zs[D * TPB];   // packed (zA, zB) per dim, [k][tid]

    const int tid = threadIdx.x;

    // Base address of coefficient table in constant space
    unsigned long long cbase;
    asm("mov.u64 %0, c_coeff;" : "=l"(cbase));

    const long r0 = (long)blockIdx.x * ROWS_PER_BLOCK + tid;
    const long r1 = r0 + TPB;
    const bool v0 = r0 < B;
    const bool v1 = r1 < B;

    // Load two z rows (16 floats each), zero-fill invalid rows, pack pairs into smem
    {
        const float4* p0 = (const float4*)(z + r0 * D);
        const float4* p1 = (const float4*)(z + r1 * D);
#pragma unroll
        for (int q = 0; q < 4; q++) {
            float4 t0 = v0 ? p0[q] : make_float4(0.f, 0.f, 0.f, 0.f);
            float4 t1 = v1 ? p1[q] : make_float4(0.f, 0.f, 0.f, 0.f);
            float a[4] = {t0.x, t0.y, t0.z, t0.w};
            float b[4] = {t1.x, t1.y, t1.z, t1.w};
#pragma unroll
            for (int s = 0; s < 4; s++) {
                unsigned long long p;
                asm("mov.b64 %0, {%1, %2};" : "=l"(p)
                    : "r"(__float_as_uint(a[s])), "r"(__float_as_uint(b[s])));
                zs[(4 * q + s) * TPB + tid] = p;
            }
        }
    }
    __syncthreads();

    // 8 packed accumulators per row; init = constant term row (theta col 0 == 1)
    unsigned long long aA[8], aB[8];
    {
        ulonglong2 i0 = ldc_v2(cbase +  0);
        ulonglong2 i1 = ldc_v2(cbase + 16);
        ulonglong2 i2 = ldc_v2(cbase + 32);
        ulonglong2 i3 = ldc_v2(cbase + 48);
        aA[0] = i0.x; aA[1] = i0.y; aA[2] = i1.x; aA[3] = i1.y;
        aA[4] = i2.x; aA[5] = i2.y; aA[6] = i3.x; aA[7] = i3.y;
#pragma unroll
        for (int p = 0; p < 8; p++) aB[p] = aA[p];
    }
    unsigned long long cptr = cbase + 64;   // byte offset of coeff row 1

    // One coefficient row: splat both monomials + 4 LDC.128 + 16 FFMA2
#define ROW(mp) do {                                                        \
        unsigned lo_, hi_; unsigned long long mA_, mB_;                     \
        asm("mov.b64 {%0, %1}, %2;" : "=r"(lo_), "=r"(hi_) : "l"(mp));      \
        asm("mov.b64 %0, {%1, %1};" : "=l"(mA_) : "r"(lo_));                \
        asm("mov.b64 %0, {%1, %1};" : "=l"(mB_) : "r"(hi_));                \
        ulonglong2 q0 = ldc_v2(cptr +  0);                                  \
        ulonglong2 q1 = ldc_v2(cptr + 16);                                  \
        ulonglong2 q2 = ldc_v2(cptr + 32);                                  \
        ulonglong2 q3 = ldc_v2(cptr + 48);                                  \
        FFMA2(aA[0], mA_, q0.x); FFMA2(aB[0], mB_, q0.x);                   \
        FFMA2(aA[1], mA_, q0.y); FFMA2(aB[1], mB_, q0.y);                   \
        FFMA2(aA[2], mA_, q1.x); FFMA2(aB[2], mB_, q1.x);                   \
        FFMA2(aA[3], mA_, q1.y); FFMA2(aB[3], mB_, q1.y);                   \
        FFMA2(aA[4], mA_, q2.x); FFMA2(aB[4], mB_, q2.x);                   \
        FFMA2(aA[5], mA_, q2.y); FFMA2(aB[5], mB_, q2.y);                   \
        FFMA2(aA[6], mA_, q3.x); FFMA2(aB[6], mB_, q3.x);                   \
        FFMA2(aA[7], mA_, q3.y); FFMA2(aB[7], mB_, q3.y);                   \
        cptr += 64;                                                         \
    } while (0)

    // ---- order 1: z_i (monomial pair comes straight from smem) ----
#pragma unroll 1
    for (int i = 0; i < D; i++) {
        unsigned long long mp = zs[i * TPB + tid];
        ROW(mp);
    }
    // ---- order 2: z_i * z_j, i<=j ----
#pragma unroll 1
    for (int i = 0; i < D; i++) {
        unsigned long long zpi = zs[i * TPB + tid];
#pragma unroll 1
        for (int j = i; j < D; j++) {
            unsigned long long mp;
            MULX2(mp, zpi, zs[j * TPB + tid]);
            ROW(mp);
        }
    }
    // ---- order 3: z_i * z_j * z_k, i<=j<=k ----
#pragma unroll 1
    for (int i = 0; i < D; i++) {
        unsigned long long zpi = zs[i * TPB + tid];
#pragma unroll 1
        for (int j = i; j < D; j++) {
            unsigned long long pp;
            MULX2(pp, zpi, zs[j * TPB + tid]);
#pragma unroll 1
            for (int k = j; k < D; k++) {
                unsigned long long mp;
                MULX2(mp, pp, zs[k * TPB + tid]);
                ROW(mp);
            }
        }
    }
#undef ROW

    // Store 16 fp32 outputs per row as 4x 16B stores
    if (v0) {
        ulonglong2* o = (ulonglong2*)(out + r0 * D);
        o[0] = make_ulonglong2(aA[0], aA[1]);
        o[1] = make_ulonglong2(aA[2], aA[3]);
        o[2] = make_ulonglong2(aA[4], aA[5]);
        o[3] = make_ulonglong2(aA[6], aA[7]);
    }
    if (v1) {
        ulonglong2* o = (ulonglong2*)(out + r1 * D);
        o[0] = make_ulonglong2(aB[0], aB[1]);
        o[1] = make_ulonglong2(aB[2], aB[3]);
        o[2] = make_ulonglong2(aB[4], aB[5]);
        o[3] = make_ulonglong2(aB[6], aB[7]);
    }
}

extern "C" void kernel_launch(void* const* d_in, const int* in_sizes, int n_in,
                              void* d_out, int out_size)
{
    const float*         z      = (const float*)d_in[0];
    const float*         coeff  = (const float*)d_in[1];
    const float*         fixedv = (const float*)d_in[2];
    const unsigned char* fmask  = (const unsigned char*)d_in[3];
    float*               out    = (float*)d_out;

    const int B = in_sizes[0] / D;

    // 1) apply fixed_mask into scratch
    prep_kernel<<<(LIB * D + 255) / 256, 256>>>(coeff, fixedv, fmask);

    // 2) scratch -> constant bank (graph-capturable D2D memcpy)
    void *sym = nullptr, *src = nullptr;
    cudaGetSymbolAddress(&sym, c_coeff);
    cudaGetSymbolAddress(&src, g_masked);
    cudaMemcpyAsync(sym, src, LIB * D * sizeof(float), cudaMemcpyDeviceToDevice, 0);

    // 3) main kernel
    const int grid = (B + ROWS_PER_BLOCK - 1) / ROWS_PER_BLOCK;
    sindy_kernel<<<grid, TPB>>>(z, out, B);
}